// round 6
// baseline (speedup 1.0000x reference)
#include <cuda_runtime.h>
#include <cstdint>

// EGES model, B=16384, D=128, K=3, S1=5, C=6. One warp per row.
// R6: L2 residency control via createpolicy + ld.global.nc.L2::cache_hint
// (the direct .L2::evict_* qualifier is restricted to 256-bit loads on this
// toolchain). Side tables (Ws0/Ws1/Ww) -> evict_last (survive in L2 across
// graph replays); streaming item-table gathers (Win/Wout) -> evict_first.

#define D4  32
#define NS1 5
#define NC  6

__device__ __forceinline__ uint64_t policy_evict_last() {
    uint64_t p;
    asm("createpolicy.fractional.L2::evict_last.b64 %0, 1.0;" : "=l"(p));
    return p;
}
__device__ __forceinline__ uint64_t policy_evict_first() {
    uint64_t p;
    asm("createpolicy.fractional.L2::evict_first.b64 %0, 1.0;" : "=l"(p));
    return p;
}
__device__ __forceinline__ float4 ldg_hint_f4(const float4* p, uint64_t pol) {
    float4 v;
    asm volatile("ld.global.nc.L2::cache_hint.v4.f32 {%0,%1,%2,%3}, [%4], %5;"
                 : "=f"(v.x), "=f"(v.y), "=f"(v.z), "=f"(v.w)
                 : "l"(p), "l"(pol));
    return v;
}
__device__ __forceinline__ float ldg_hint_f(const float* p, uint64_t pol) {
    float v;
    asm volatile("ld.global.nc.L2::cache_hint.f32 %0, [%1], %2;"
                 : "=f"(v) : "l"(p), "l"(pol));
    return v;
}

__global__ __launch_bounds__(256, 6)
void eges_kernel(const int* __restrict__ central,
                 const int* __restrict__ side0,
                 const int* __restrict__ side1,
                 const int* __restrict__ ctx,
                 const float4* __restrict__ Win,
                 const float4* __restrict__ Wout,
                 const float* __restrict__ Ww,
                 const float4* __restrict__ Ws0,
                 const float4* __restrict__ Ws1,
                 float* __restrict__ out,
                 int B)
{
    const int warp = (blockIdx.x * blockDim.x + threadIdx.x) >> 5;
    const int lane = threadIdx.x & 31;
    if (warp >= B) return;
    const int b = warp;

    const uint64_t POL_F = policy_evict_first();
    const uint64_t POL_L = policy_evict_last();

    // ---- indices (uniform within warp; L1 broadcast) ----
    const int ci = __ldg(&central[b]);
    const int i0 = __ldg(&side0[b]);
    int cc[NC];
#pragma unroll
    for (int j = 0; j < NC; ++j) cc[j] = __ldg(&ctx[b * NC + j]);

    // ---- front-batch the DRAM gathers: item row + 6 context rows (streaming) ----
    const float4 item = ldg_hint_f4(&Win[(size_t)ci * D4 + lane], POL_F);
    float4 ov[NC];
#pragma unroll
    for (int j = 0; j < NC; ++j) ov[j] = ldg_hint_f4(&Wout[(size_t)cc[j] * D4 + lane], POL_F);

    // softmax weights (keep resident in L2)
    const float w0r = ldg_hint_f(&Ww[(size_t)ci * 3 + 0], POL_L);
    const float w1r = ldg_hint_f(&Ww[(size_t)ci * 3 + 1], POL_L);
    const float w2r = ldg_hint_f(&Ww[(size_t)ci * 3 + 2], POL_L);

    // ---- side tables: keep resident in L2 ----
    const float4 e0 = ldg_hint_f4(&Ws0[(size_t)i0 * D4 + lane], POL_L);

    float4 e1;
    {
        const int j0 = __ldg(&side1[b * NS1 + 0]);
        const int j1 = __ldg(&side1[b * NS1 + 1]);
        float4 a = ldg_hint_f4(&Ws1[(size_t)j0 * D4 + lane], POL_L);
        float4 c = ldg_hint_f4(&Ws1[(size_t)j1 * D4 + lane], POL_L);
        e1.x = a.x + c.x; e1.y = a.y + c.y; e1.z = a.z + c.z; e1.w = a.w + c.w;
        const int j2 = __ldg(&side1[b * NS1 + 2]);
        const int j3 = __ldg(&side1[b * NS1 + 3]);
        a = ldg_hint_f4(&Ws1[(size_t)j2 * D4 + lane], POL_L);
        c = ldg_hint_f4(&Ws1[(size_t)j3 * D4 + lane], POL_L);
        e1.x += a.x + c.x; e1.y += a.y + c.y; e1.z += a.z + c.z; e1.w += a.w + c.w;
        const int j4 = __ldg(&side1[b * NS1 + 4]);
        a = ldg_hint_f4(&Ws1[(size_t)j4 * D4 + lane], POL_L);
        e1.x = (e1.x + a.x) * 0.2f;
        e1.y = (e1.y + a.y) * 0.2f;
        e1.z = (e1.z + a.z) * 0.2f;
        e1.w = (e1.w + a.w) * 0.2f;
    }

    // ---- stable softmax over 3 weights ----
    const float m  = fmaxf(w0r, fmaxf(w1r, w2r));
    const float x0 = __expf(w0r - m), x1 = __expf(w1r - m), x2 = __expf(w2r - m);
    const float inv = 1.0f / (x0 + x1 + x2);
    const float w0 = x0 * inv, w1 = x1 * inv, w2 = x2 * inv;

    // ---- hidden ----
    float4 h;
    h.x = w0 * item.x + w1 * e0.x + w2 * e1.x;
    h.y = w0 * item.y + w1 * e0.y + w2 * e1.y;
    h.z = w0 * item.z + w1 * e0.z + w2 * e1.z;
    h.w = w0 * item.w + w1 * e0.w + w2 * e1.w;

    // ---- 6 dots + interleaved butterfly reductions ----
    float d0 = h.x * ov[0].x + h.y * ov[0].y + h.z * ov[0].z + h.w * ov[0].w;
    float d1 = h.x * ov[1].x + h.y * ov[1].y + h.z * ov[1].z + h.w * ov[1].w;
    float d2 = h.x * ov[2].x + h.y * ov[2].y + h.z * ov[2].z + h.w * ov[2].w;
    float d3 = h.x * ov[3].x + h.y * ov[3].y + h.z * ov[3].z + h.w * ov[3].w;
    float d4 = h.x * ov[4].x + h.y * ov[4].y + h.z * ov[4].z + h.w * ov[4].w;
    float d5 = h.x * ov[5].x + h.y * ov[5].y + h.z * ov[5].z + h.w * ov[5].w;

#pragma unroll
    for (int off = 16; off > 0; off >>= 1) {
        d0 += __shfl_xor_sync(0xFFFFFFFFu, d0, off);
        d1 += __shfl_xor_sync(0xFFFFFFFFu, d1, off);
        d2 += __shfl_xor_sync(0xFFFFFFFFu, d2, off);
        d3 += __shfl_xor_sync(0xFFFFFFFFu, d3, off);
        d4 += __shfl_xor_sync(0xFFFFFFFFu, d4, off);
        d5 += __shfl_xor_sync(0xFFFFFFFFu, d5, off);
    }

    if (lane == 0) {
        float2* o2 = (float2*)(out + (size_t)b * NC);   // 24B row stride -> 8B aligned
        float2 p;
        p.x = 1.0f / (1.0f + __expf(-d0));
        p.y = 1.0f / (1.0f + __expf(-d1));
        o2[0] = p;
        p.x = 1.0f / (1.0f + __expf(-d2));
        p.y = 1.0f / (1.0f + __expf(-d3));
        o2[1] = p;
        p.x = 1.0f / (1.0f + __expf(-d4));
        p.y = 1.0f / (1.0f + __expf(-d5));
        o2[2] = p;
    }
}

extern "C" void kernel_launch(void* const* d_in, const int* in_sizes, int n_in,
                              void* d_out, int out_size)
{
    const int*    central = (const int*)d_in[0];
    const int*    side0   = (const int*)d_in[1];
    const int*    side1   = (const int*)d_in[2];
    const int*    ctx     = (const int*)d_in[3];
    const float4* Win     = (const float4*)d_in[4];
    const float4* Wout    = (const float4*)d_in[5];
    const float*  Ww      = (const float*)d_in[6];
    const float4* Ws0     = (const float4*)d_in[7];
    const float4* Ws1     = (const float4*)d_in[8];
    float* out = (float*)d_out;

    const int B = in_sizes[0];
    const int blocks = (B + 7) / 8;   // 8 warps/block
    eges_kernel<<<blocks, 256>>>(central, side0, side1, ctx,
                                 Win, Wout, Ww, Ws0, Ws1, out, B);
}

// round 7
// speedup vs baseline: 1.0097x; 1.0097x over previous
#include <cuda_runtime.h>
#include <cstdint>

// EGES model, B=16384, D=128, K=3, S1=5, C=6. One warp per row.
// R7: __ldcs (cache-streaming, evict-first) on the two 512MB item tables so the
// 57MB/replay random stream stops thrashing the reusable side tables
// (Ws1=25.6MB, Ww=12MB, Ws0=0.5MB) out of the ~126MB L2. Side tables use __ldg.

#define D4  32
#define NS1 5
#define NC  6

__global__ __launch_bounds__(256, 6)
void eges_kernel(const int* __restrict__ central,
                 const int* __restrict__ side0,
                 const int* __restrict__ side1,
                 const int* __restrict__ ctx,
                 const float4* __restrict__ Win,
                 const float4* __restrict__ Wout,
                 const float* __restrict__ Ww,
                 const float4* __restrict__ Ws0,
                 const float4* __restrict__ Ws1,
                 float* __restrict__ out,
                 int B)
{
    const int warp = (blockIdx.x * blockDim.x + threadIdx.x) >> 5;
    const int lane = threadIdx.x & 31;
    if (warp >= B) return;
    const int b = warp;

    // ---- indices (uniform within warp; L1 broadcast) ----
    const int ci = __ldg(&central[b]);
    const int i0 = __ldg(&side0[b]);
    int cc[NC];
#pragma unroll
    for (int j = 0; j < NC; ++j) cc[j] = __ldg(&ctx[b * NC + j]);

    // ---- streaming DRAM gathers (evict-first): item row + 6 context rows ----
    const float4 item = __ldcs(&Win[(size_t)ci * D4 + lane]);
    float4 ov[NC];
#pragma unroll
    for (int j = 0; j < NC; ++j) ov[j] = __ldcs(&Wout[(size_t)cc[j] * D4 + lane]);

    // softmax weights (reused table -> default caching)
    const float w0r = __ldg(&Ww[(size_t)ci * 3 + 0]);
    const float w1r = __ldg(&Ww[(size_t)ci * 3 + 1]);
    const float w2r = __ldg(&Ww[(size_t)ci * 3 + 2]);

    // ---- side tables (reused across replays -> default caching) ----
    const float4 e0 = __ldg(&Ws0[(size_t)i0 * D4 + lane]);

    float4 e1;
    {
        const int j0 = __ldg(&side1[b * NS1 + 0]);
        const int j1 = __ldg(&side1[b * NS1 + 1]);
        float4 a = __ldg(&Ws1[(size_t)j0 * D4 + lane]);
        float4 c = __ldg(&Ws1[(size_t)j1 * D4 + lane]);
        e1.x = a.x + c.x; e1.y = a.y + c.y; e1.z = a.z + c.z; e1.w = a.w + c.w;
        const int j2 = __ldg(&side1[b * NS1 + 2]);
        const int j3 = __ldg(&side1[b * NS1 + 3]);
        a = __ldg(&Ws1[(size_t)j2 * D4 + lane]);
        c = __ldg(&Ws1[(size_t)j3 * D4 + lane]);
        e1.x += a.x + c.x; e1.y += a.y + c.y; e1.z += a.z + c.z; e1.w += a.w + c.w;
        const int j4 = __ldg(&side1[b * NS1 + 4]);
        a = __ldg(&Ws1[(size_t)j4 * D4 + lane]);
        e1.x = (e1.x + a.x) * 0.2f;
        e1.y = (e1.y + a.y) * 0.2f;
        e1.z = (e1.z + a.z) * 0.2f;
        e1.w = (e1.w + a.w) * 0.2f;
    }

    // ---- stable softmax over 3 weights ----
    const float m  = fmaxf(w0r, fmaxf(w1r, w2r));
    const float x0 = __expf(w0r - m), x1 = __expf(w1r - m), x2 = __expf(w2r - m);
    const float inv = 1.0f / (x0 + x1 + x2);
    const float w0 = x0 * inv, w1 = x1 * inv, w2 = x2 * inv;

    // ---- hidden ----
    float4 h;
    h.x = w0 * item.x + w1 * e0.x + w2 * e1.x;
    h.y = w0 * item.y + w1 * e0.y + w2 * e1.y;
    h.z = w0 * item.z + w1 * e0.z + w2 * e1.z;
    h.w = w0 * item.w + w1 * e0.w + w2 * e1.w;

    // ---- 6 dots + interleaved butterfly reductions ----
    float d0 = h.x * ov[0].x + h.y * ov[0].y + h.z * ov[0].z + h.w * ov[0].w;
    float d1 = h.x * ov[1].x + h.y * ov[1].y + h.z * ov[1].z + h.w * ov[1].w;
    float d2 = h.x * ov[2].x + h.y * ov[2].y + h.z * ov[2].z + h.w * ov[2].w;
    float d3 = h.x * ov[3].x + h.y * ov[3].y + h.z * ov[3].z + h.w * ov[3].w;
    float d4 = h.x * ov[4].x + h.y * ov[4].y + h.z * ov[4].z + h.w * ov[4].w;
    float d5 = h.x * ov[5].x + h.y * ov[5].y + h.z * ov[5].z + h.w * ov[5].w;

#pragma unroll
    for (int off = 16; off > 0; off >>= 1) {
        d0 += __shfl_xor_sync(0xFFFFFFFFu, d0, off);
        d1 += __shfl_xor_sync(0xFFFFFFFFu, d1, off);
        d2 += __shfl_xor_sync(0xFFFFFFFFu, d2, off);
        d3 += __shfl_xor_sync(0xFFFFFFFFu, d3, off);
        d4 += __shfl_xor_sync(0xFFFFFFFFu, d4, off);
        d5 += __shfl_xor_sync(0xFFFFFFFFu, d5, off);
    }

    if (lane == 0) {
        float2* o2 = (float2*)(out + (size_t)b * NC);   // 24B row stride -> 8B aligned
        float2 p;
        p.x = 1.0f / (1.0f + __expf(-d0));
        p.y = 1.0f / (1.0f + __expf(-d1));
        o2[0] = p;
        p.x = 1.0f / (1.0f + __expf(-d2));
        p.y = 1.0f / (1.0f + __expf(-d3));
        o2[1] = p;
        p.x = 1.0f / (1.0f + __expf(-d4));
        p.y = 1.0f / (1.0f + __expf(-d5));
        o2[2] = p;
    }
}

extern "C" void kernel_launch(void* const* d_in, const int* in_sizes, int n_in,
                              void* d_out, int out_size)
{
    const int*    central = (const int*)d_in[0];
    const int*    side0   = (const int*)d_in[1];
    const int*    side1   = (const int*)d_in[2];
    const int*    ctx     = (const int*)d_in[3];
    const float4* Win     = (const float4*)d_in[4];
    const float4* Wout    = (const float4*)d_in[5];
    const float*  Ww      = (const float*)d_in[6];
    const float4* Ws0     = (const float4*)d_in[7];
    const float4* Ws1     = (const float4*)d_in[8];
    float* out = (float*)d_out;

    const int B = in_sizes[0];
    const int blocks = (B + 7) / 8;   // 8 warps/block
    eges_kernel<<<blocks, 256>>>(central, side0, side1, ctx,
                                 Win, Wout, Ww, Ws0, Ws1, out, B);
}

// round 8
// speedup vs baseline: 1.1482x; 1.1372x over previous
#include <cuda_runtime.h>
#include <cstdint>

// EGES model, B=16384, D=128, K=3, S1=5, C=6.
// R8: half-warp per row with 256-bit gathers (ld.global.nc.v8.b32), which is
// the ONLY load width sm_100a accepts direct .L2::evict_* qualifiers on
// (per R5 ptxas diagnostic). Stream tables (Win/Wout) -> evict_first,
// reused side tables (Ws0/Ws1) -> evict_last.

#define NS1 5
#define NC  6
#define ROW_FLOATS 128

struct F8 { float f[8]; };

__device__ __forceinline__ F8 ldg256_ef(const float* p) {   // evict_first
    uint32_t a0,a1,a2,a3,a4,a5,a6,a7;
    asm volatile("ld.global.nc.L2::evict_first.v8.b32 {%0,%1,%2,%3,%4,%5,%6,%7}, [%8];"
                 : "=r"(a0),"=r"(a1),"=r"(a2),"=r"(a3),
                   "=r"(a4),"=r"(a5),"=r"(a6),"=r"(a7) : "l"(p));
    F8 r;
    r.f[0]=__uint_as_float(a0); r.f[1]=__uint_as_float(a1);
    r.f[2]=__uint_as_float(a2); r.f[3]=__uint_as_float(a3);
    r.f[4]=__uint_as_float(a4); r.f[5]=__uint_as_float(a5);
    r.f[6]=__uint_as_float(a6); r.f[7]=__uint_as_float(a7);
    return r;
}
__device__ __forceinline__ F8 ldg256_el(const float* p) {   // evict_last
    uint32_t a0,a1,a2,a3,a4,a5,a6,a7;
    asm volatile("ld.global.nc.L2::evict_last.v8.b32 {%0,%1,%2,%3,%4,%5,%6,%7}, [%8];"
                 : "=r"(a0),"=r"(a1),"=r"(a2),"=r"(a3),
                   "=r"(a4),"=r"(a5),"=r"(a6),"=r"(a7) : "l"(p));
    F8 r;
    r.f[0]=__uint_as_float(a0); r.f[1]=__uint_as_float(a1);
    r.f[2]=__uint_as_float(a2); r.f[3]=__uint_as_float(a3);
    r.f[4]=__uint_as_float(a4); r.f[5]=__uint_as_float(a5);
    r.f[6]=__uint_as_float(a6); r.f[7]=__uint_as_float(a7);
    return r;
}

__global__ __launch_bounds__(128)
void eges_kernel(const int* __restrict__ central,
                 const int* __restrict__ side0,
                 const int* __restrict__ side1,
                 const int* __restrict__ ctx,
                 const float* __restrict__ Win,
                 const float* __restrict__ Wout,
                 const float* __restrict__ Ww,
                 const float* __restrict__ Ws0,
                 const float* __restrict__ Ws1,
                 float* __restrict__ out,
                 int B)
{
    const int warp = (blockIdx.x * blockDim.x + threadIdx.x) >> 5;
    const int lane = threadIdx.x & 31;
    const int half = lane >> 4;          // 0 or 1: which row this lane serves
    const int hl   = lane & 15;          // lane within half-warp
    const int b    = warp * 2 + half;    // row index (B=16384 is even)
    if (b >= B) return;

    const int off = hl * 8;              // float offset within the 128-float row

    // ---- indices (uniform within each half-warp) ----
    const int ci = __ldg(&central[b]);
    const int i0 = __ldg(&side0[b]);
    int cc[NC];
#pragma unroll
    for (int j = 0; j < NC; ++j) cc[j] = __ldg(&ctx[b * NC + j]);

    // ---- front-batch streaming gathers: item + 6 ctx (evict_first) ----
    const F8 item = ldg256_ef(Win + (size_t)ci * ROW_FLOATS + off);
    F8 ov[NC];
#pragma unroll
    for (int j = 0; j < NC; ++j)
        ov[j] = ldg256_ef(Wout + (size_t)cc[j] * ROW_FLOATS + off);

    // softmax weights
    const float w0r = __ldg(&Ww[(size_t)ci * 3 + 0]);
    const float w1r = __ldg(&Ww[(size_t)ci * 3 + 1]);
    const float w2r = __ldg(&Ww[(size_t)ci * 3 + 2]);

    // ---- reused side tables (evict_last) ----
    const F8 e0 = ldg256_el(Ws0 + (size_t)i0 * ROW_FLOATS + off);

    F8 e1;
    {
        const int j0 = __ldg(&side1[b * NS1 + 0]);
        const int j1 = __ldg(&side1[b * NS1 + 1]);
        F8 a = ldg256_el(Ws1 + (size_t)j0 * ROW_FLOATS + off);
        F8 c = ldg256_el(Ws1 + (size_t)j1 * ROW_FLOATS + off);
#pragma unroll
        for (int k = 0; k < 8; ++k) e1.f[k] = a.f[k] + c.f[k];
        const int j2 = __ldg(&side1[b * NS1 + 2]);
        const int j3 = __ldg(&side1[b * NS1 + 3]);
        a = ldg256_el(Ws1 + (size_t)j2 * ROW_FLOATS + off);
        c = ldg256_el(Ws1 + (size_t)j3 * ROW_FLOATS + off);
#pragma unroll
        for (int k = 0; k < 8; ++k) e1.f[k] += a.f[k] + c.f[k];
        const int j4 = __ldg(&side1[b * NS1 + 4]);
        a = ldg256_el(Ws1 + (size_t)j4 * ROW_FLOATS + off);
#pragma unroll
        for (int k = 0; k < 8; ++k) e1.f[k] = (e1.f[k] + a.f[k]) * 0.2f;
    }

    // ---- stable softmax over 3 weights ----
    const float m  = fmaxf(w0r, fmaxf(w1r, w2r));
    const float x0 = __expf(w0r - m), x1 = __expf(w1r - m), x2 = __expf(w2r - m);
    const float inv = 1.0f / (x0 + x1 + x2);
    const float w0 = x0 * inv, w1 = x1 * inv, w2 = x2 * inv;

    // ---- hidden (8 floats per lane) ----
    F8 h;
#pragma unroll
    for (int k = 0; k < 8; ++k)
        h.f[k] = w0 * item.f[k] + w1 * e0.f[k] + w2 * e1.f[k];

    // ---- 6 dots (partial per lane) ----
    float d[NC];
#pragma unroll
    for (int c = 0; c < NC; ++c) {
        float s = 0.f;
#pragma unroll
        for (int k = 0; k < 8; ++k) s += h.f[k] * ov[c].f[k];
        d[c] = s;
    }

    // reduce within each 16-lane half-warp (xor offsets stay inside the half)
#pragma unroll
    for (int offr = 8; offr > 0; offr >>= 1) {
#pragma unroll
        for (int c = 0; c < NC; ++c)
            d[c] += __shfl_xor_sync(0xFFFFFFFFu, d[c], offr);
    }

    if (hl == 0) {   // lane 0 writes row 2w, lane 16 writes row 2w+1
        float2* o2 = (float2*)(out + (size_t)b * NC);   // 24B stride -> 8B aligned
        float2 p;
        p.x = 1.0f / (1.0f + __expf(-d[0]));
        p.y = 1.0f / (1.0f + __expf(-d[1]));
        o2[0] = p;
        p.x = 1.0f / (1.0f + __expf(-d[2]));
        p.y = 1.0f / (1.0f + __expf(-d[3]));
        o2[1] = p;
        p.x = 1.0f / (1.0f + __expf(-d[4]));
        p.y = 1.0f / (1.0f + __expf(-d[5]));
        o2[2] = p;
    }
}

extern "C" void kernel_launch(void* const* d_in, const int* in_sizes, int n_in,
                              void* d_out, int out_size)
{
    const int*   central = (const int*)d_in[0];
    const int*   side0   = (const int*)d_in[1];
    const int*   side1   = (const int*)d_in[2];
    const int*   ctx     = (const int*)d_in[3];
    const float* Win     = (const float*)d_in[4];
    const float* Wout    = (const float*)d_in[5];
    const float* Ww      = (const float*)d_in[6];
    const float* Ws0     = (const float*)d_in[7];
    const float* Ws1     = (const float*)d_in[8];
    float* out = (float*)d_out;

    const int B = in_sizes[0];
    const int rows_per_block = (128 / 32) * 2;          // 4 warps * 2 rows
    const int blocks = (B + rows_per_block - 1) / rows_per_block;
    eges_kernel<<<blocks, 128>>>(central, side0, side1, ctx,
                                 Win, Wout, Ww, Ws0, Ws1, out, B);
}

// round 11
// speedup vs baseline: 1.1559x; 1.0067x over previous
#include <cuda_runtime.h>
#include <cstdint>

// EGES model, B=16384, D=128, K=3, S1=5, C=6.
// R9 (3rd submit; two infra failures, zero perf signal): half-warp per row +
// 256-bit gathers (kept from R8), with the 6 context gathers split into two
// waves of 3 to cut the register peak (95 -> ~72) and raise occupancy
// (27% -> ~40%) — testing whether a latency residual remains at v8
// granularity. evict_first on item-table stream, evict_last on side tables.

#define NS1 5
#define NC  6
#define ROW_FLOATS 128

struct F8 { float f[8]; };

__device__ __forceinline__ F8 ldg256_ef(const float* p) {   // evict_first
    uint32_t a0,a1,a2,a3,a4,a5,a6,a7;
    asm volatile("ld.global.nc.L2::evict_first.v8.b32 {%0,%1,%2,%3,%4,%5,%6,%7}, [%8];"
                 : "=r"(a0),"=r"(a1),"=r"(a2),"=r"(a3),
                   "=r"(a4),"=r"(a5),"=r"(a6),"=r"(a7) : "l"(p));
    F8 r;
    r.f[0]=__uint_as_float(a0); r.f[1]=__uint_as_float(a1);
    r.f[2]=__uint_as_float(a2); r.f[3]=__uint_as_float(a3);
    r.f[4]=__uint_as_float(a4); r.f[5]=__uint_as_float(a5);
    r.f[6]=__uint_as_float(a6); r.f[7]=__uint_as_float(a7);
    return r;
}
__device__ __forceinline__ F8 ldg256_el(const float* p) {   // evict_last
    uint32_t a0,a1,a2,a3,a4,a5,a6,a7;
    asm volatile("ld.global.nc.L2::evict_last.v8.b32 {%0,%1,%2,%3,%4,%5,%6,%7}, [%8];"
                 : "=r"(a0),"=r"(a1),"=r"(a2),"=r"(a3),
                   "=r"(a4),"=r"(a5),"=r"(a6),"=r"(a7) : "l"(p));
    F8 r;
    r.f[0]=__uint_as_float(a0); r.f[1]=__uint_as_float(a1);
    r.f[2]=__uint_as_float(a2); r.f[3]=__uint_as_float(a3);
    r.f[4]=__uint_as_float(a4); r.f[5]=__uint_as_float(a5);
    r.f[6]=__uint_as_float(a6); r.f[7]=__uint_as_float(a7);
    return r;
}

__global__ __launch_bounds__(128, 7)
void eges_kernel(const int* __restrict__ central,
                 const int* __restrict__ side0,
                 const int* __restrict__ side1,
                 const int* __restrict__ ctx,
                 const float* __restrict__ Win,
                 const float* __restrict__ Wout,
                 const float* __restrict__ Ww,
                 const float* __restrict__ Ws0,
                 const float* __restrict__ Ws1,
                 float* __restrict__ out,
                 int B)
{
    const int warp = (blockIdx.x * blockDim.x + threadIdx.x) >> 5;
    const int lane = threadIdx.x & 31;
    const int half = lane >> 4;
    const int hl   = lane & 15;
    const int b    = warp * 2 + half;
    if (b >= B) return;

    const int off = hl * 8;

    // ---- indices ----
    const int ci = __ldg(&central[b]);
    const int i0 = __ldg(&side0[b]);
    int cc[NC];
#pragma unroll
    for (int j = 0; j < NC; ++j) cc[j] = __ldg(&ctx[b * NC + j]);

    // ---- wave-0 front batch: item + ctx0..2 (DRAM, evict_first) + side0 ----
    const F8 item = ldg256_ef(Win + (size_t)ci * ROW_FLOATS + off);
    F8 ov0 = ldg256_ef(Wout + (size_t)cc[0] * ROW_FLOATS + off);
    F8 ov1 = ldg256_ef(Wout + (size_t)cc[1] * ROW_FLOATS + off);
    F8 ov2 = ldg256_ef(Wout + (size_t)cc[2] * ROW_FLOATS + off);
    const F8 e0 = ldg256_el(Ws0 + (size_t)i0 * ROW_FLOATS + off);

    const float w0r = __ldg(&Ww[(size_t)ci * 3 + 0]);
    const float w1r = __ldg(&Ww[(size_t)ci * 3 + 1]);
    const float w2r = __ldg(&Ww[(size_t)ci * 3 + 2]);

    // ---- side1 mean: one F8 temp at a time (L2-resident, latency cheap) ----
    F8 e1;
    {
        const int j0 = __ldg(&side1[b * NS1 + 0]);
        F8 a = ldg256_el(Ws1 + (size_t)j0 * ROW_FLOATS + off);
#pragma unroll
        for (int k = 0; k < 8; ++k) e1.f[k] = a.f[k];
        const int j1 = __ldg(&side1[b * NS1 + 1]);
        a = ldg256_el(Ws1 + (size_t)j1 * ROW_FLOATS + off);
#pragma unroll
        for (int k = 0; k < 8; ++k) e1.f[k] += a.f[k];
        const int j2 = __ldg(&side1[b * NS1 + 2]);
        a = ldg256_el(Ws1 + (size_t)j2 * ROW_FLOATS + off);
#pragma unroll
        for (int k = 0; k < 8; ++k) e1.f[k] += a.f[k];
        const int j3 = __ldg(&side1[b * NS1 + 3]);
        a = ldg256_el(Ws1 + (size_t)j3 * ROW_FLOATS + off);
#pragma unroll
        for (int k = 0; k < 8; ++k) e1.f[k] += a.f[k];
        const int j4 = __ldg(&side1[b * NS1 + 4]);
        a = ldg256_el(Ws1 + (size_t)j4 * ROW_FLOATS + off);
#pragma unroll
        for (int k = 0; k < 8; ++k) e1.f[k] = (e1.f[k] + a.f[k]) * 0.2f;
    }

    // ---- softmax + hidden ----
    const float m  = fmaxf(w0r, fmaxf(w1r, w2r));
    const float x0 = __expf(w0r - m), x1 = __expf(w1r - m), x2 = __expf(w2r - m);
    const float inv = 1.0f / (x0 + x1 + x2);
    const float w0 = x0 * inv, w1 = x1 * inv, w2 = x2 * inv;

    F8 h;
#pragma unroll
    for (int k = 0; k < 8; ++k)
        h.f[k] = w0 * item.f[k] + w1 * e0.f[k] + w2 * e1.f[k];

    // ---- wave-1 dots (consume ov0..2, freeing registers) ----
    float d0 = 0.f, d1 = 0.f, d2 = 0.f;
#pragma unroll
    for (int k = 0; k < 8; ++k) {
        d0 += h.f[k] * ov0.f[k];
        d1 += h.f[k] * ov1.f[k];
        d2 += h.f[k] * ov2.f[k];
    }

    // ---- wave-2 ctx gathers ----
    ov0 = ldg256_ef(Wout + (size_t)cc[3] * ROW_FLOATS + off);
    ov1 = ldg256_ef(Wout + (size_t)cc[4] * ROW_FLOATS + off);
    ov2 = ldg256_ef(Wout + (size_t)cc[5] * ROW_FLOATS + off);

    float d3 = 0.f, d4 = 0.f, d5 = 0.f;
#pragma unroll
    for (int k = 0; k < 8; ++k) {
        d3 += h.f[k] * ov0.f[k];
        d4 += h.f[k] * ov1.f[k];
        d5 += h.f[k] * ov2.f[k];
    }

    // ---- reduce within each 16-lane half ----
#pragma unroll
    for (int offr = 8; offr > 0; offr >>= 1) {
        d0 += __shfl_xor_sync(0xFFFFFFFFu, d0, offr);
        d1 += __shfl_xor_sync(0xFFFFFFFFu, d1, offr);
        d2 += __shfl_xor_sync(0xFFFFFFFFu, d2, offr);
        d3 += __shfl_xor_sync(0xFFFFFFFFu, d3, offr);
        d4 += __shfl_xor_sync(0xFFFFFFFFu, d4, offr);
        d5 += __shfl_xor_sync(0xFFFFFFFFu, d5, offr);
    }

    if (hl == 0) {
        float2* o2 = (float2*)(out + (size_t)b * NC);
        float2 p;
        p.x = 1.0f / (1.0f + __expf(-d0));
        p.y = 1.0f / (1.0f + __expf(-d1));
        o2[0] = p;
        p.x = 1.0f / (1.0f + __expf(-d2));
        p.y = 1.0f / (1.0f + __expf(-d3));
        o2[1] = p;
        p.x = 1.0f / (1.0f + __expf(-d4));
        p.y = 1.0f / (1.0f + __expf(-d5));
        o2[2] = p;
    }
}

extern "C" void kernel_launch(void* const* d_in, const int* in_sizes, int n_in,
                              void* d_out, int out_size)
{
    const int*   central = (const int*)d_in[0];
    const int*   side0   = (const int*)d_in[1];
    const int*   side1   = (const int*)d_in[2];
    const int*   ctx     = (const int*)d_in[3];
    const float* Win     = (const float*)d_in[4];
    const float* Wout    = (const float*)d_in[5];
    const float* Ww      = (const float*)d_in[6];
    const float* Ws0     = (const float*)d_in[7];
    const float* Ws1     = (const float*)d_in[8];
    float* out = (float*)d_out;

    const int B = in_sizes[0];
    const int rows_per_block = (128 / 32) * 2;   // 4 warps * 2 rows
    const int blocks = (B + rows_per_block - 1) / rows_per_block;
    eges_kernel<<<blocks, 128>>>(central, side0, side1, ctx,
                                 Win, Wout, Ww, Ws0, Ws1, out, B);
}